// round 16
// baseline (speedup 1.0000x reference)
#include <cuda_runtime.h>
#include <cuda_bf16.h>
#include <math.h>
#include <stdint.h>

// Problem constants
#define Bc 4
#define Sc 512
#define Dc 512
#define Hc 4
#define Vc 32000
#define Rc (Bc*Sc)    // 2048 query rows
#define HDc (Hc*Dc)   // 2048
#define NSPLIT 20
#define K3 1536       // 3*512 split triple
#define K6 6144       // 3*2048 split triple

// ---------------- scratch (device globals) ----------------
__device__ float d_e[Rc*Dc];
__device__ float d_krnp[(size_t)2*Hc*Sc*Sc];          // krn split-K partials
__device__ float d_fk[Rc*Dc];
__device__ float d_part[(size_t)4*Rc*Dc];             // fp32 partials (W_o)
__device__ __nv_bfloat16 d_partb[(size_t)NSPLIT*Rc*Dc]; // bf16 partials (num)
__device__ float d_cmeanp[32*Dc];
__device__ float d_cmean[Dc];
__device__ float d_last[Bc*Dc];
__device__ __nv_bfloat16 d_E[(size_t)Rc*Vc];
__device__ __nv_bfloat16 d_wte_bf[(size_t)Vc*Dc];
__device__ __nv_bfloat16 d_wteT_bf[(size_t)Dc*Vc];
__device__ __nv_bfloat16 d_fk_bf[Rc*Dc];
__device__ float d_denp[(Vc/128)*Rc];
__device__ float d_den[Rc];
// split-bf16 buffers
__device__ __nv_bfloat16 d_p3[(size_t)(Sc+1)*K3];
__device__ __nv_bfloat16 d_wqk3t[(size_t)2*Hc*Dc*K3]; // [which][h][e][k] (hi,lo,hi)
__device__ __nv_bfloat16 d_QK3[(size_t)2*Hc*Sc*K3];   // Q triple (hi,hi,lo), K triple (hi,lo,hi)
__device__ __nv_bfloat16 d_krn3[(size_t)Hc*Sc*K3];    // coef * softmax(krn), triple
__device__ __nv_bfloat16 d_vm3t[(size_t)Bc*Dc*K3];
__device__ __nv_bfloat16 d_delta3[(size_t)Rc*K6];
__device__ __nv_bfloat16 d_wo3t[(size_t)Dc*K6];

// =================== PTX helpers ===================
__device__ __forceinline__ uint32_t smem_u32(const void* p){
    uint32_t a;
    asm("{ .reg .u64 t; cvta.to.shared.u64 t, %1; cvt.u32.u64 %0, t; }":"=r"(a):"l"(p));
    return a;
}
__device__ __forceinline__ void cp16(uint32_t s, const void* g){
    asm volatile("cp.async.cg.shared.global [%0], [%1], 16;"::"r"(s),"l"(g));
}
__device__ __forceinline__ void cp_commit(){ asm volatile("cp.async.commit_group;"); }
template<int N> __device__ __forceinline__ void cp_wait(){ asm volatile("cp.async.wait_group %0;"::"n"(N)); }

__device__ __forceinline__ void ldm_x4(uint32_t& r0,uint32_t& r1,uint32_t& r2,uint32_t& r3,uint32_t addr){
    asm volatile("ldmatrix.sync.aligned.m8n8.x4.shared.b16 {%0,%1,%2,%3}, [%4];"
      : "=r"(r0),"=r"(r1),"=r"(r2),"=r"(r3) : "r"(addr));
}
__device__ __forceinline__ void mma16816(float* c, uint32_t a0,uint32_t a1,uint32_t a2,uint32_t a3,
                                         uint32_t b0,uint32_t b1){
    asm volatile("mma.sync.aligned.m16n8k16.row.col.f32.bf16.bf16.f32 "
      "{%0,%1,%2,%3}, {%4,%5,%6,%7}, {%8,%9}, {%0,%1,%2,%3};"
      : "+f"(c[0]),"+f"(c[1]),"+f"(c[2]),"+f"(c[3])
      : "r"(a0),"r"(a1),"r"(a2),"r"(a3),"r"(b0),"r"(b1));
}

// =================== 128x128 bf16 HMMA GEMM, BK=64, 3-stage, 1 sync/tile ===================
// C[128,128] per CTA = A(128 x K) @ B(128 x K)^T, both K-major bf16.
// MODE 0: exp epilogue -> bf16 Eout (ld Vc) + row-sum partials denPart.
// MODE 1: fp32 -> Cout + z*(Rc*Dc), split-K chunk z (kTiles of 64).
// MODE 2: bf16 -> Eout + z*(Rc*Dc), split-K chunk z.
// MODE 3: split-bf16 triple -> Eout(ldC), pattern 0:(hi,hi,lo) 1:(hi,lo,hi)
//         2: use zhi as pattern; coefFlag=1 -> causal k-tile skipping
//         (A lower-triangular in 3x512 segments); z via strides.
// MODE 5: raw fp32 -> Cout; z via strides; pattern=1 -> triangular x/y grid decode.
#define PITCH 144            // 128 B data + 16 pad; conflict-free ldmatrix
#define ABUF  18432          // 128 * 144
#define TBUF  36864          // A + B per stage
#define CORE_SMEM (3*TBUF)   // 110592

template<int MODE>
__global__ void __launch_bounds__(256, 2)
mma_core(const __nv_bfloat16* __restrict__ A, long lda,
         const __nv_bfloat16* __restrict__ B, long ldb,
         int kTiles,
         __nv_bfloat16* __restrict__ Eout, float* __restrict__ denPart,
         float* __restrict__ Cout, long ldC,
         int zdiv, long sAlo, long sAhi, long sBlo, long sBhi, long sClo, long sChi,
         int pattern, int seg, int coefFlag, float scale)
{
    extern __shared__ char smem[];
    const uint32_t sb = smem_u32(smem);
    const int tid = threadIdx.x, lane = tid & 31, wid = tid >> 5;
    const int wm = wid & 1, wn = wid >> 1;
    const int wmBase = wm * 64, wnBase = wn * 32;
    int rowBase = blockIdx.y << 7, colBase = blockIdx.x << 7;
    long k0base = 0;
    int zhi = 0;
    if (MODE == 1 || MODE == 2){
        k0base = (long)blockIdx.z * kTiles * 64;
        if (MODE == 1) Cout += (size_t)blockIdx.z * ((size_t)Rc*Dc);
        else           Eout += (size_t)blockIdx.z * ((size_t)Rc*Dc);
    } else if (MODE == 3 || MODE == 5){
        int lo = blockIdx.z % zdiv; zhi = blockIdx.z / zdiv;
        A += (size_t)lo * sAlo + (long)zhi * sAhi;
        B += (size_t)lo * sBlo + (long)zhi * sBhi;
        if (MODE == 3) Eout += (size_t)lo * sClo + (long)zhi * sChi;
        else           Cout += (size_t)lo * sClo + (long)zhi * sChi;
        if (MODE == 5 && pattern){           // triangular block decode (xb <= yb)
            int i = blockIdx.x, yb = 0, acc = 0;
            while (acc + yb + 1 <= i){ acc += yb + 1; yb++; }
            rowBase = yb << 7; colBase = (i - acc) << 7;
        }
    }

    // causal k-tile mapping (MODE 3, coefFlag): tiles enumerate
    // seg-major over 3 segments of 512 elems, kPer 64-elem tiles per segment.
    int nT = kTiles, kPer = kTiles;
    if (MODE == 3 && coefFlag){
        kPer = 2 * (int)blockIdx.y + 2;
        nT = 3 * kPer;
    }
    auto kof = [&](int t)->long{
        int sg = t / kPer, tt = t - sg * kPer;
        return k0base + (long)sg * 512 + (long)tt * 64;
    };

    float acc[4][4][4];
#pragma unroll
    for (int mt = 0; mt < 4; mt++)
#pragma unroll
        for (int nt = 0; nt < 4; nt++)
#pragma unroll
            for (int q = 0; q < 4; q++) acc[mt][nt][q] = 0.f;

    const int ar = lane & 15;
    const int akof = (lane >> 4) * 8;
    const int bn = (lane & 7) + ((lane & 16) ? 8 : 0);
    const int bkof = ((lane >> 3) & 1) * 8;

    auto load = [&](int slot, long k0){
        uint32_t base = sb + slot*TBUF;
#pragma unroll
        for (int i = 0; i < 4; i++){
            int c = tid + i*256; int r = c >> 3, s = c & 7;
            cp16(base + r*PITCH + s*16, A + (size_t)(rowBase + r)*lda + k0 + s*8);
        }
#pragma unroll
        for (int i = 0; i < 4; i++){
            int c = tid + i*256; int r = c >> 3, s = c & 7;
            cp16(base + ABUF + r*PITCH + s*16, B + (size_t)(colBase + r)*ldb + k0 + s*8);
        }
        cp_commit();
    };

    load(0, kof(0));
    load(1, kof(1));
    for (int t = 0; t < nT; t++){
        if (t + 1 < nT) cp_wait<1>(); else cp_wait<0>();
        __syncthreads();
        uint32_t base = sb + (t % 3)*TBUF;
#pragma unroll
        for (int kk = 0; kk < 4; kk++){
            uint32_t a[4][4], b[2][4];
            uint32_t aCol = (uint32_t)((kk*16 + akof) * 2);
            uint32_t bCol = (uint32_t)((kk*16 + bkof) * 2);
#pragma unroll
            for (int mt = 0; mt < 4; mt++)
                ldm_x4(a[mt][0], a[mt][1], a[mt][2], a[mt][3],
                       base + (uint32_t)(wmBase + mt*16 + ar)*PITCH + aCol);
#pragma unroll
            for (int j = 0; j < 2; j++)
                ldm_x4(b[j][0], b[j][1], b[j][2], b[j][3],
                       base + ABUF + (uint32_t)(wnBase + j*16 + bn)*PITCH + bCol);
#pragma unroll
            for (int mt = 0; mt < 4; mt++)
#pragma unroll
                for (int nt = 0; nt < 4; nt++)
                    mma16816(acc[mt][nt], a[mt][0], a[mt][1], a[mt][2], a[mt][3],
                             b[nt>>1][(nt&1)*2], b[nt>>1][(nt&1)*2 + 1]);
        }
        // no bottom sync: slot (t+2)%3 == (t-1)%3 was consumed before this
        // iteration's top barrier, so overwriting it is race-free.
        if (t + 2 < nT) load((t + 2) % 3, kof(t + 2));
    }

    int cq = (lane & 3) * 2;
    if (MODE == 0){
        __syncthreads();                          // smem reused for den reduce
        float* denm = (float*)smem;
#pragma unroll
        for (int mt = 0; mt < 4; mt++){
            int lr0 = wmBase + mt*16 + (lane >> 2);
            int r0 = rowBase + lr0;
            float s0 = 0.f, s1 = 0.f;
#pragma unroll
            for (int nt = 0; nt < 4; nt++){
                int col = colBase + wnBase + nt*8 + cq;
                float e0 = __expf(fminf(acc[mt][nt][0], 70.f));
                float e1 = __expf(fminf(acc[mt][nt][1], 70.f));
                float e2 = __expf(fminf(acc[mt][nt][2], 70.f));
                float e3 = __expf(fminf(acc[mt][nt][3], 70.f));
                s0 += e0 + e1; s1 += e2 + e3;
                *(__nv_bfloat162*)(Eout + (size_t)r0*Vc + col) =
                    __float22bfloat162_rn(make_float2(e0, e1));
                *(__nv_bfloat162*)(Eout + (size_t)(r0+8)*Vc + col) =
                    __float22bfloat162_rn(make_float2(e2, e3));
            }
            s0 += __shfl_xor_sync(0xffffffffu, s0, 1);
            s0 += __shfl_xor_sync(0xffffffffu, s0, 2);
            s1 += __shfl_xor_sync(0xffffffffu, s1, 1);
            s1 += __shfl_xor_sync(0xffffffffu, s1, 2);
            if ((lane & 3) == 0){
                denm[lr0*4 + wn] = s0;
                denm[(lr0+8)*4 + wn] = s1;
            }
        }
        __syncthreads();
        if (tid < 128){
            float d = denm[tid*4] + denm[tid*4+1] + denm[tid*4+2] + denm[tid*4+3];
            denPart[(size_t)blockIdx.x * Rc + rowBase + tid] = d;
        }
    } else if (MODE == 1 || MODE == 5){
#pragma unroll
        for (int mt = 0; mt < 4; mt++){
            int r0 = rowBase + wmBase + mt*16 + (lane >> 2);
#pragma unroll
            for (int nt = 0; nt < 4; nt++){
                int col = colBase + wnBase + nt*8 + cq;
                *(float2*)(Cout + (size_t)r0*ldC + col) =
                    make_float2(acc[mt][nt][0], acc[mt][nt][1]);
                *(float2*)(Cout + (size_t)(r0+8)*ldC + col) =
                    make_float2(acc[mt][nt][2], acc[mt][nt][3]);
            }
        }
    } else if (MODE == 2){
#pragma unroll
        for (int mt = 0; mt < 4; mt++){
            int r0 = rowBase + wmBase + mt*16 + (lane >> 2);
#pragma unroll
            for (int nt = 0; nt < 4; nt++){
                int col = colBase + wnBase + nt*8 + cq;
                *(__nv_bfloat162*)(Eout + (size_t)r0*ldC + col) =
                    __float22bfloat162_rn(make_float2(acc[mt][nt][0], acc[mt][nt][1]));
                *(__nv_bfloat162*)(Eout + (size_t)(r0+8)*ldC + col) =
                    __float22bfloat162_rn(make_float2(acc[mt][nt][2], acc[mt][nt][3]));
            }
        }
    } else if (MODE == 3){
        int pat = (pattern == 2) ? zhi : pattern;
#pragma unroll
        for (int mt = 0; mt < 4; mt++){
            int r0 = rowBase + wmBase + mt*16 + (lane >> 2);
#pragma unroll
            for (int nt = 0; nt < 4; nt++){
                int col = colBase + wnBase + nt*8 + cq;
                float v0 = acc[mt][nt][0], v1 = acc[mt][nt][1];
                float v2 = acc[mt][nt][2], v3 = acc[mt][nt][3];
                __nv_bfloat16 h0 = __float2bfloat16(v0), h1 = __float2bfloat16(v1);
                __nv_bfloat16 h2 = __float2bfloat16(v2), h3 = __float2bfloat16(v3);
                __nv_bfloat16 l0 = __float2bfloat16(v0 - __bfloat162float(h0));
                __nv_bfloat16 l1 = __float2bfloat16(v1 - __bfloat162float(h1));
                __nv_bfloat16 l2 = __float2bfloat16(v2 - __bfloat162float(h2));
                __nv_bfloat16 l3 = __float2bfloat16(v3 - __bfloat162float(h3));
                __nv_bfloat162 hp0 = __halves2bfloat162(h0, h1);
                __nv_bfloat162 lp0 = __halves2bfloat162(l0, l1);
                __nv_bfloat162 hp1 = __halves2bfloat162(h2, h3);
                __nv_bfloat162 lp1 = __halves2bfloat162(l2, l3);
                __nv_bfloat16* rr0 = Eout + (size_t)r0*ldC + col;
                __nv_bfloat16* rr1 = Eout + (size_t)(r0+8)*ldC + col;
                *(__nv_bfloat162*)(rr0) = hp0;
                *(__nv_bfloat162*)(rr1) = hp1;
                if (pat == 0){
                    *(__nv_bfloat162*)(rr0 + seg)   = hp0;
                    *(__nv_bfloat162*)(rr0 + 2*seg) = lp0;
                    *(__nv_bfloat162*)(rr1 + seg)   = hp1;
                    *(__nv_bfloat162*)(rr1 + 2*seg) = lp1;
                } else {
                    *(__nv_bfloat162*)(rr0 + seg)   = lp0;
                    *(__nv_bfloat162*)(rr0 + 2*seg) = hp0;
                    *(__nv_bfloat162*)(rr1 + seg)   = lp1;
                    *(__nv_bfloat162*)(rr1 + 2*seg) = hp1;
                }
            }
        }
    }
}

// ---------------- reductions / elementwise ----------------
__device__ __forceinline__ float warpSum(float v) {
#pragma unroll
    for (int o = 16; o; o >>= 1) v += __shfl_xor_sync(0xffffffffu, v, o);
    return v;
}
__device__ __forceinline__ float warpMax(float v) {
#pragma unroll
    for (int o = 16; o; o >>= 1) v = fmaxf(v, __shfl_xor_sync(0xffffffffu, v, o));
    return v;
}

__global__ void ln_rows(const float* __restrict__ base, const int* __restrict__ idx,
                        const float* __restrict__ g, float* __restrict__ dst,
                        long rowStride)
{
    int row = blockIdx.x;
    const float* src = base + (idx ? (size_t)idx[row] * rowStride
                                   : (size_t)row * rowStride);
    int tid = threadIdx.x, lane = tid & 31, w = tid >> 5;
    __shared__ float sb[8];
    float v0 = src[tid], v1 = src[tid + 256];
    float s = warpSum(v0 + v1);
    if (lane == 0) sb[w] = s;
    __syncthreads();
    float tot = 0.f;
#pragma unroll
    for (int i = 0; i < 8; i++) tot += sb[i];
    float m = tot * (1.f / 512.f);
    float a0 = v0 - m, a1 = v1 - m;
    __syncthreads();
    float q = warpSum(a0*a0 + a1*a1);
    if (lane == 0) sb[w] = q;
    __syncthreads();
    float var = 0.f;
#pragma unroll
    for (int i = 0; i < 8; i++) var += sb[i];
    var *= (1.f / 512.f);
    float inv = rsqrtf(var + 1e-5f);
    float* dr = dst + (size_t)row * 512;
    dr[tid]       = a0 * inv * g[tid];
    dr[tid + 256] = a1 * inv * g[tid + 256];
}

// fused: LN(wpe row) -> split triple (hi,hi,lo) into p3
__global__ void ln_p3(const float* __restrict__ wpe, const float* __restrict__ g)
{
    int row = blockIdx.x;
    const float* src = wpe + (size_t)row * Dc;
    int tid = threadIdx.x, lane = tid & 31, w = tid >> 5;
    __shared__ float sb[8];
    float v0 = src[tid], v1 = src[tid + 256];
    float s = warpSum(v0 + v1);
    if (lane == 0) sb[w] = s;
    __syncthreads();
    float tot = 0.f;
#pragma unroll
    for (int i = 0; i < 8; i++) tot += sb[i];
    float m = tot * (1.f / 512.f);
    float a0 = v0 - m, a1 = v1 - m;
    __syncthreads();
    float q = warpSum(a0*a0 + a1*a1);
    if (lane == 0) sb[w] = q;
    __syncthreads();
    float var = 0.f;
#pragma unroll
    for (int i = 0; i < 8; i++) var += sb[i];
    var *= (1.f / 512.f);
    float inv = rsqrtf(var + 1e-5f);
    float x0 = a0 * inv * g[tid];
    float x1 = a1 * inv * g[tid + 256];
    __nv_bfloat16 h0 = __float2bfloat16(x0);
    __nv_bfloat16 l0 = __float2bfloat16(x0 - __bfloat162float(h0));
    __nv_bfloat16 h1 = __float2bfloat16(x1);
    __nv_bfloat16 l1 = __float2bfloat16(x1 - __bfloat162float(h1));
    __nv_bfloat16* r = d_p3 + (size_t)row * K3;
    r[tid] = h0;       r[512 + tid] = h0;       r[1024 + tid] = l0;
    r[tid + 256] = h1; r[768 + tid] = h1;       r[1280 + tid] = l1;
}

// fused: sum krn split-K partials, scale+clip+mask, softmax, *coef,
//        write split triple (hi,hi,lo) into krn3
__global__ void softmax_krn3()
{
    const float attnScale = 0.044194173824159216f;   // 1/sqrt(512)
    int row = blockIdx.x;                            // h*512 + s
    int s_idx = row & 511;
    const float* ra = d_krnp + (size_t)row * Sc;
    const float* rb = ra + (size_t)Hc * Sc * Sc;
    int tid = threadIdx.x, lane = tid & 31, w = tid >> 5;
    __shared__ float sb[8];
    float v0 = fminf(10.f, fmaxf(-10.f, (ra[tid] + rb[tid]) * attnScale));
    float v1 = fminf(10.f, fmaxf(-10.f, (ra[tid+256] + rb[tid+256]) * attnScale));
    if (tid > s_idx)       v0 = -INFINITY;
    if (tid + 256 > s_idx) v1 = -INFINITY;
    float m = warpMax(fmaxf(v0, v1));
    if (lane == 0) sb[w] = m;
    __syncthreads();
    float bm = sb[0];
#pragma unroll
    for (int i = 1; i < 8; i++) bm = fmaxf(bm, sb[i]);
    __syncthreads();
    float e0 = __expf(v0 - bm), e1 = __expf(v1 - bm);
    float s = warpSum(e0 + e1);
    if (lane == 0) sb[w] = s;
    __syncthreads();
    float bs = 0.f;
#pragma unroll
    for (int i = 0; i < 8; i++) bs += sb[i];
    float coef = 1.0f / (1.0f + (float)s_idx);
    float inv = coef / bs;
    float p0 = e0 * inv, p1 = e1 * inv;
    __nv_bfloat16 h0 = __float2bfloat16(p0);
    __nv_bfloat16 l0 = __float2bfloat16(p0 - __bfloat162float(h0));
    __nv_bfloat16 h1 = __float2bfloat16(p1);
    __nv_bfloat16 l1 = __float2bfloat16(p1 - __bfloat162float(h1));
    __nv_bfloat16* r3 = d_krn3 + (size_t)row * K3;
    r3[tid] = h0;  r3[512 + tid] = h0;  r3[1024 + tid] = l0;
    r3[tid + 256] = h1;  r3[768 + tid] = h1;  r3[1280 + tid] = l1;
}

__global__ void col_mean_part(const float* __restrict__ wte)
{
    int d = blockIdx.x * 128 + threadIdx.x;
    int z = blockIdx.y;
    float s = 0.f;
    int v0 = z * 1000;
    for (int v = v0; v < v0 + 1000; v++) s += wte[(size_t)v * Dc + d];
    d_cmeanp[z * Dc + d] = s;
}
__global__ void col_mean_reduce()
{
    int d = blockIdx.x * 128 + threadIdx.x;
    float s = 0.f;
#pragma unroll
    for (int z = 0; z < 32; z++) s += d_cmeanp[z * Dc + d];
    d_cmean[d] = s * (1.f / 32000.f);
}

__global__ void den_reduce()
{
    int r = blockIdx.x * 256 + threadIdx.x;
    float s = 0.f;
    for (int x = 0; x < Vc/128; x++) s += d_denp[(size_t)x * Rc + r];
    d_den[r] = s;
}

// fk += sum of 4 split-K partials (W_o); also refresh bf16 copy
__global__ void fk_combine()
{
    int i = blockIdx.x * 256 + threadIdx.x;
    float s = d_fk[i]
            + d_part[i]
            + d_part[(size_t)(Rc*Dc) + i]
            + d_part[2*(size_t)(Rc*Dc) + i]
            + d_part[3*(size_t)(Rc*Dc) + i];
    d_fk[i] = s;
    d_fk_bf[i] = __float2bfloat16(s);
}

// one-shot wte -> bf16 copy + bf16 transpose (single read of fp32)
__global__ void wte_convert(const float* __restrict__ w)
{
    __shared__ float t[32][33];
    int v0 = blockIdx.x * 32, d0 = blockIdx.y * 32;
    int tx = threadIdx.x, ty = threadIdx.y;
    for (int i = ty; i < 32; i += 8){
        float x = w[(size_t)(v0 + i) * Dc + d0 + tx];
        t[i][tx] = x;
        d_wte_bf[(size_t)(v0 + i) * Dc + d0 + tx] = __float2bfloat16(x);
    }
    __syncthreads();
    for (int i = ty; i < 32; i += 8)
        d_wteT_bf[(size_t)(d0 + i) * Vc + v0 + tx] = __float2bfloat16(t[tx][i]);
}

// ---- split-bf16 builders ----
__global__ void wqk3t_build(const float* __restrict__ W_q, const float* __restrict__ W_k)
{
    __shared__ float tl[32][33];
    int z = blockIdx.z;
    int h = z & 3, which = z >> 2;
    const float* src = (which ? W_k : W_q) + (size_t)h * Dc * Dc;
    __nv_bfloat16* dst = d_wqk3t + (size_t)which * Hc * Dc * K3 + (size_t)h * Dc * K3;
    int d0 = blockIdx.x * 32, e0 = blockIdx.y * 32;
    int tx = threadIdx.x, ty = threadIdx.y;
    for (int i = ty; i < 32; i += 8) tl[i][tx] = src[(size_t)(d0 + i) * Dc + e0 + tx];
    __syncthreads();
    for (int i = ty; i < 32; i += 8){
        float x = tl[tx][i];
        __nv_bfloat16 hi = __float2bfloat16(x);
        __nv_bfloat16 lo = __float2bfloat16(x - __bfloat162float(hi));
        __nv_bfloat16* row = dst + (size_t)(e0 + i) * K3;
        row[d0 + tx] = hi; row[512 + d0 + tx] = lo; row[1024 + d0 + tx] = hi;
    }
}

// vm3t[b][d][k] = split-transpose of (e - correction); triple (hi,lo,hi)
__global__ void vm3t_build(int layerN)
{
    __shared__ float tl[32][33];
    int b = blockIdx.z;
    int t0 = blockIdx.x * 32, d0 = blockIdx.y * 32;
    int tx = threadIdx.x, ty = threadIdx.y;
    for (int i = ty; i < 32; i += 8){
        int r = b * Sc + t0 + i;
        int d = d0 + tx;
        float corr;
        if (layerN){
            float num = 0.f;
#pragma unroll
            for (int z = 0; z < NSPLIT; z++)
                num += __bfloat162float(
                    d_partb[(size_t)z * ((size_t)Rc*Dc) + (size_t)r * Dc + d]);
            corr = num / d_den[r];
        } else {
            corr = d_cmean[d];
        }
        tl[i][tx] = d_e[(size_t)r * Dc + d] - corr;
    }
    __syncthreads();
    __nv_bfloat16* dst = d_vm3t + (size_t)b * Dc * K3;
    for (int i = ty; i < 32; i += 8){
        float x = tl[tx][i];
        __nv_bfloat16 hi = __float2bfloat16(x);
        __nv_bfloat16 lo = __float2bfloat16(x - __bfloat162float(hi));
        __nv_bfloat16* row = dst + (size_t)(d0 + i) * K3;
        row[t0 + tx] = hi; row[512 + t0 + tx] = lo; row[1024 + t0 + tx] = hi;
    }
}

__global__ void wo3t_build(const float* __restrict__ W_o)
{
    int i = blockIdx.x * 256 + threadIdx.x;
    int k = i & 2047, n = i >> 11;
    float x = W_o[i];
    __nv_bfloat16 hi = __float2bfloat16(x);
    __nv_bfloat16 lo = __float2bfloat16(x - __bfloat162float(hi));
    __nv_bfloat16* row = d_wo3t + (size_t)n * K6;
    row[k] = hi; row[2048 + k] = lo; row[4096 + k] = hi;
}

__global__ void logits_kernel(const float* __restrict__ last,
                              const float* __restrict__ wte,
                              float* __restrict__ out)
{
    int w = threadIdx.x >> 5, lane = threadIdx.x & 31;
    int v = blockIdx.x * 8 + w;
    int b = blockIdx.y;
    const float* q = last + b * 512;
    const float* wr = wte + (size_t)v * 512;
    float s = 0.f;
#pragma unroll
    for (int d = lane; d < 512; d += 32) s = fmaf(q[d], wr[d], s);
    s = warpSum(s);
    if (lane == 0) out[(size_t)b * Vc + v] = s;
}

// ---------------- launch ----------------
extern "C" void kernel_launch(void* const* d_in, const int* in_sizes, int n_in,
                              void* d_out, int out_size)
{
    const int*   x   = (const int*)  d_in[0];
    const float* wte = (const float*)d_in[1];
    const float* wpe = (const float*)d_in[2];
    const float* g_e = (const float*)d_in[3];
    const float* g_p = (const float*)d_in[4];
    const float* g_f = (const float*)d_in[5];
    const float* W_q = (const float*)d_in[6];
    const float* W_k = (const float*)d_in[7];
    const float* W_o = (const float*)d_in[8];
    float* out = (float*)d_out;

    float *e, *krnp, *fk, *part, *last, *denp;
    __nv_bfloat16 *E, *wte_bf, *wteT_bf, *fk_bf, *partb;
    __nv_bfloat16 *p3, *wqk3t, *QK3, *krn3, *vm3t, *delta3, *wo3t;
    cudaGetSymbolAddress((void**)&e,     d_e);
    cudaGetSymbolAddress((void**)&krnp,  d_krnp);
    cudaGetSymbolAddress((void**)&fk,    d_fk);
    cudaGetSymbolAddress((void**)&part,  d_part);
    cudaGetSymbolAddress((void**)&partb, d_partb);
    cudaGetSymbolAddress((void**)&last,  d_last);
    cudaGetSymbolAddress((void**)&denp,  d_denp);
    cudaGetSymbolAddress((void**)&E,       d_E);
    cudaGetSymbolAddress((void**)&wte_bf,  d_wte_bf);
    cudaGetSymbolAddress((void**)&wteT_bf, d_wteT_bf);
    cudaGetSymbolAddress((void**)&fk_bf,   d_fk_bf);
    cudaGetSymbolAddress((void**)&p3,      d_p3);
    cudaGetSymbolAddress((void**)&wqk3t,   d_wqk3t);
    cudaGetSymbolAddress((void**)&QK3,     d_QK3);
    cudaGetSymbolAddress((void**)&krn3,    d_krn3);
    cudaGetSymbolAddress((void**)&vm3t,    d_vm3t);
    cudaGetSymbolAddress((void**)&delta3,  d_delta3);
    cudaGetSymbolAddress((void**)&wo3t,    d_wo3t);

    cudaFuncSetAttribute(mma_core<0>, cudaFuncAttributeMaxDynamicSharedMemorySize, CORE_SMEM);
    cudaFuncSetAttribute(mma_core<1>, cudaFuncAttributeMaxDynamicSharedMemorySize, CORE_SMEM);
    cudaFuncSetAttribute(mma_core<2>, cudaFuncAttributeMaxDynamicSharedMemorySize, CORE_SMEM);
    cudaFuncSetAttribute(mma_core<3>, cudaFuncAttributeMaxDynamicSharedMemorySize, CORE_SMEM);
    cudaFuncSetAttribute(mma_core<5>, cudaFuncAttributeMaxDynamicSharedMemorySize, CORE_SMEM);

    const long SS = (long)Sc * Sc;

    // QK chain
    ln_p3<<<Sc+1, 256>>>(wpe, g_p);
    wqk3t_build<<<dim3(16,16,8), dim3(32,8)>>>(W_q, W_k);
    // QK3: z = which*4 + h;  Q (which=0): A = p3+K3, pattern 0
    //                        K (which=1): A = p3   , pattern 1
    mma_core<3><<<dim3(4,4,8), 256, CORE_SMEM>>>(
        p3 + K3, (long)K3, wqk3t, (long)K3, K3/64,
        QK3, nullptr, nullptr, (long)K3,
        4, 0, -(long)K3,
        (long)Dc*K3, (long)Hc*Dc*K3,
        (long)Sc*K3, (long)Hc*Sc*K3,
        2, 512, 0, 0.f);
    // krn raw partials: triangular blocks only (10 of 16); z = chunk*4 + h
    mma_core<5><<<dim3(10,1,8), 256, CORE_SMEM>>>(
        QK3, (long)K3, QK3 + (size_t)Hc*Sc*K3, (long)K3, 768/64,
        nullptr, nullptr, krnp, (long)Sc,
        4, (long)Sc*K3, 768,
        (long)Sc*K3, 768,
        SS, (long)Hc*SS,
        1, 0, 0, 0.f);
    softmax_krn3<<<Hc*Sc, 256>>>();

    // embeddings + layer-0 mean + wte conversions
    ln_rows<<<Rc, 256>>>(wte, x, g_e, e, (long)Dc);
    col_mean_part<<<dim3(4, 32), 128>>>(wte);
    col_mean_reduce<<<4, 128>>>();
    wte_convert<<<dim3(Vc/32, Dc/32), dim3(32, 8)>>>(wte);
    wo3t_build<<<(Dc*HDc)/256, 256>>>(W_o);

    cudaMemsetAsync(fk, 0, (size_t)Rc * Dc * sizeof(float), 0);
    cudaMemsetAsync(fk_bf, 0, (size_t)Rc * Dc * sizeof(__nv_bfloat16), 0);

    for (int layer = 0; layer < 4; layer++) {
        if (layer > 0) {
            // E = exp(f_k @ wte^T), fused row-sum partials (K=512 -> 8 tiles)
            mma_core<0><<<dim3(Vc/128, Rc/128, 1), 256, CORE_SMEM>>>(
                fk_bf, (long)Dc, wte_bf, (long)Dc, Dc/64,
                E, denp, nullptr, 0, 1, 0,0,0,0,0,0, 0,0,0,0.f);
            den_reduce<<<Rc/256, 256>>>();
            // num = E @ wte (split-K over NSPLIT chunks; bf16 partials)
            mma_core<2><<<dim3(Dc/128, Rc/128, NSPLIT), 256, CORE_SMEM>>>(
                E, (long)Vc, wteT_bf, (long)Vc, (Vc/NSPLIT)/64,
                partb, nullptr, nullptr, (long)Dc, 1, 0,0,0,0,0,0, 0,0,0,0.f);
        }
        // vm3t = split-transpose(e - ex_wte)  (fused combine)
        vm3t_build<<<dim3(16,16,4), dim3(32,8)>>>(layer > 0 ? 1 : 0);
        // delta3 = split(krn3[h] @ vm3t[b]^T); causal k-tile skipping
        mma_core<3><<<dim3(4,4,16), 256, CORE_SMEM>>>(
            krn3, (long)K3, vm3t, (long)K3, K3/64,
            delta3, nullptr, nullptr, (long)K6,
            4, (long)Sc*K3, 0, 0, (long)Dc*K3, (long)Dc, (long)Sc*K6,
            0, 2048, 1, 0.f);
        // f_k += delta @ W_o^T (4-way split-K; fp32 partials)
        mma_core<1><<<dim3(Dc/128, Rc/128, 4), 256, CORE_SMEM>>>(
            delta3, (long)K6, wo3t, (long)K6, K6/(4*64),
            nullptr, nullptr, part, (long)Dc, 1, 0,0,0,0,0,0, 0,0,0,0.f);
        fk_combine<<<Rc*Dc/256, 256>>>();
    }

    ln_rows<<<Bc, 256>>>(fk + (size_t)(Sc-1)*Dc, nullptr, g_f, last, (long)Sc*Dc);
    logits_kernel<<<dim3(Vc/8, Bc), 256>>>(last, wte, out);
}

// round 17
// speedup vs baseline: 1.0383x; 1.0383x over previous
#include <cuda_runtime.h>
#include <cuda_bf16.h>
#include <math.h>
#include <stdint.h>

// Problem constants
#define Bc 4
#define Sc 512
#define Dc 512
#define Hc 4
#define Vc 32000
#define Rc (Bc*Sc)    // 2048 query rows
#define HDc (Hc*Dc)   // 2048
#define NSPLIT 20
#define K3 1536       // 3*512 split triple
#define K6 6144       // 3*2048 split triple

// ---------------- scratch (device globals) ----------------
__device__ float d_e[Rc*Dc];
__device__ float d_krnp[(size_t)2*Hc*Sc*Sc];          // krn split-K partials
__device__ float d_fk[Rc*Dc];
__device__ float d_part[(size_t)4*Rc*Dc];             // fp32 partials (W_o)
__device__ __nv_bfloat16 d_partb[(size_t)NSPLIT*Rc*Dc]; // bf16 partials (num)
__device__ float d_cmeanp[32*Dc];
__device__ float d_cmean[Dc];
__device__ float d_last[Bc*Dc];
__device__ __nv_bfloat16 d_E[(size_t)Rc*Vc];
__device__ __nv_bfloat16 d_wte_bf[(size_t)Vc*Dc];
__device__ __nv_bfloat16 d_wteT_bf[(size_t)Dc*Vc];
__device__ __nv_bfloat16 d_fk_bf[Rc*Dc];
__device__ float d_denp[(Vc/128)*Rc];
__device__ float d_den[Rc];
// split-bf16 buffers
__device__ __nv_bfloat16 d_p3[(size_t)(Sc+1)*K3];
__device__ __nv_bfloat16 d_wqk3t[(size_t)2*Hc*Dc*K3]; // [which][h][e][k] (hi,lo,hi)
__device__ __nv_bfloat16 d_QK3[(size_t)2*Hc*Sc*K3];   // Q triple (hi,hi,lo), K triple (hi,lo,hi)
__device__ __nv_bfloat16 d_krn3[(size_t)Hc*Sc*K3];    // coef * softmax(krn), triple
__device__ __nv_bfloat16 d_vm3t[(size_t)Bc*Dc*K3];
__device__ __nv_bfloat16 d_delta3[(size_t)Rc*K6];
__device__ __nv_bfloat16 d_wo3t[(size_t)Dc*K6];

// =================== PTX helpers ===================
__device__ __forceinline__ uint32_t smem_u32(const void* p){
    uint32_t a;
    asm("{ .reg .u64 t; cvta.to.shared.u64 t, %1; cvt.u32.u64 %0, t; }":"=r"(a):"l"(p));
    return a;
}
__device__ __forceinline__ void cp16(uint32_t s, const void* g){
    asm volatile("cp.async.cg.shared.global [%0], [%1], 16;"::"r"(s),"l"(g));
}
__device__ __forceinline__ void cp_commit(){ asm volatile("cp.async.commit_group;"); }
template<int N> __device__ __forceinline__ void cp_wait(){ asm volatile("cp.async.wait_group %0;"::"n"(N)); }

__device__ __forceinline__ void ldm_x4(uint32_t& r0,uint32_t& r1,uint32_t& r2,uint32_t& r3,uint32_t addr){
    asm volatile("ldmatrix.sync.aligned.m8n8.x4.shared.b16 {%0,%1,%2,%3}, [%4];"
      : "=r"(r0),"=r"(r1),"=r"(r2),"=r"(r3) : "r"(addr));
}
__device__ __forceinline__ void mma16816(float* c, uint32_t a0,uint32_t a1,uint32_t a2,uint32_t a3,
                                         uint32_t b0,uint32_t b1){
    asm volatile("mma.sync.aligned.m16n8k16.row.col.f32.bf16.bf16.f32 "
      "{%0,%1,%2,%3}, {%4,%5,%6,%7}, {%8,%9}, {%0,%1,%2,%3};"
      : "+f"(c[0]),"+f"(c[1]),"+f"(c[2]),"+f"(c[3])
      : "r"(a0),"r"(a1),"r"(a2),"r"(a3),"r"(b0),"r"(b1));
}

// =================== 128x128 bf16 HMMA GEMM, BK=64, 3-stage, 1 sync/tile ===================
// C[128,128] per CTA = A(128 x K) @ B(128 x K)^T, both K-major bf16.
// MODE 0: exp epilogue -> bf16 Eout (ld Vc) + row-sum partials denPart.
// MODE 1: fp32 -> Cout + z*(Rc*Dc), split-K chunk z (kTiles of 64).
// MODE 2: bf16 -> Eout + z*(Rc*Dc), split-K chunk z.
// MODE 3: split-bf16 triple -> Eout(ldC), pattern 0:(hi,hi,lo) 1:(hi,lo,hi)
//         2: use zhi as pattern; z via strides.
// MODE 5: raw fp32 -> Cout; z via strides (krn split-K partials).
#define PITCH 144            // 128 B data + 16 pad; conflict-free ldmatrix
#define ABUF  18432          // 128 * 144
#define TBUF  36864          // A + B per stage
#define CORE_SMEM (3*TBUF)   // 110592

template<int MODE>
__global__ void __launch_bounds__(256, 2)
mma_core(const __nv_bfloat16* __restrict__ A, long lda,
         const __nv_bfloat16* __restrict__ B, long ldb,
         int kTiles,
         __nv_bfloat16* __restrict__ Eout, float* __restrict__ denPart,
         float* __restrict__ Cout, long ldC,
         int zdiv, long sAlo, long sAhi, long sBlo, long sBhi, long sClo, long sChi,
         int pattern, int seg, int coefFlag, float scale)
{
    extern __shared__ char smem[];
    const uint32_t sb = smem_u32(smem);
    const int tid = threadIdx.x, lane = tid & 31, wid = tid >> 5;
    const int wm = wid & 1, wn = wid >> 1;
    const int wmBase = wm * 64, wnBase = wn * 32;
    const int rowBase = blockIdx.y << 7, colBase = blockIdx.x << 7;
    long k0base = 0;
    int zhi = 0;
    if (MODE == 1 || MODE == 2){
        k0base = (long)blockIdx.z * kTiles * 64;
        if (MODE == 1) Cout += (size_t)blockIdx.z * ((size_t)Rc*Dc);
        else           Eout += (size_t)blockIdx.z * ((size_t)Rc*Dc);
    } else if (MODE == 3 || MODE == 5){
        int lo = blockIdx.z % zdiv; zhi = blockIdx.z / zdiv;
        A += (size_t)lo * sAlo + (long)zhi * sAhi;
        B += (size_t)lo * sBlo + (long)zhi * sBhi;
        if (MODE == 3) Eout += (size_t)lo * sClo + (long)zhi * sChi;
        else           Cout += (size_t)lo * sClo + (long)zhi * sChi;
    }

    float acc[4][4][4];
#pragma unroll
    for (int mt = 0; mt < 4; mt++)
#pragma unroll
        for (int nt = 0; nt < 4; nt++)
#pragma unroll
            for (int q = 0; q < 4; q++) acc[mt][nt][q] = 0.f;

    const int ar = lane & 15;
    const int akof = (lane >> 4) * 8;
    const int bn = (lane & 7) + ((lane & 16) ? 8 : 0);
    const int bkof = ((lane >> 3) & 1) * 8;

    auto load = [&](int slot, long k0){
        uint32_t base = sb + slot*TBUF;
#pragma unroll
        for (int i = 0; i < 4; i++){
            int c = tid + i*256; int r = c >> 3, s = c & 7;
            cp16(base + r*PITCH + s*16, A + (size_t)(rowBase + r)*lda + k0 + s*8);
        }
#pragma unroll
        for (int i = 0; i < 4; i++){
            int c = tid + i*256; int r = c >> 3, s = c & 7;
            cp16(base + ABUF + r*PITCH + s*16, B + (size_t)(colBase + r)*ldb + k0 + s*8);
        }
        cp_commit();
    };

    load(0, k0base);
    load(1, k0base + 64);
    for (int t = 0; t < kTiles; t++){
        if (t + 1 < kTiles) cp_wait<1>(); else cp_wait<0>();
        __syncthreads();
        uint32_t base = sb + (t % 3)*TBUF;
#pragma unroll
        for (int kk = 0; kk < 4; kk++){
            uint32_t a[4][4], b[2][4];
            uint32_t aCol = (uint32_t)((kk*16 + akof) * 2);
            uint32_t bCol = (uint32_t)((kk*16 + bkof) * 2);
#pragma unroll
            for (int mt = 0; mt < 4; mt++)
                ldm_x4(a[mt][0], a[mt][1], a[mt][2], a[mt][3],
                       base + (uint32_t)(wmBase + mt*16 + ar)*PITCH + aCol);
#pragma unroll
            for (int j = 0; j < 2; j++)
                ldm_x4(b[j][0], b[j][1], b[j][2], b[j][3],
                       base + ABUF + (uint32_t)(wnBase + j*16 + bn)*PITCH + bCol);
#pragma unroll
            for (int mt = 0; mt < 4; mt++)
#pragma unroll
                for (int nt = 0; nt < 4; nt++)
                    mma16816(acc[mt][nt], a[mt][0], a[mt][1], a[mt][2], a[mt][3],
                             b[nt>>1][(nt&1)*2], b[nt>>1][(nt&1)*2 + 1]);
        }
        // no bottom sync: slot (t+2)%3 == (t-1)%3 was consumed before this
        // iteration's top barrier, so overwriting it is race-free.
        if (t + 2 < kTiles) load((t + 2) % 3, k0base + (long)(t+2)*64);
    }

    int cq = (lane & 3) * 2;
    if (MODE == 0){
        __syncthreads();                          // smem reused for den reduce
        float* denm = (float*)smem;
#pragma unroll
        for (int mt = 0; mt < 4; mt++){
            int lr0 = wmBase + mt*16 + (lane >> 2);
            int r0 = rowBase + lr0;
            float s0 = 0.f, s1 = 0.f;
#pragma unroll
            for (int nt = 0; nt < 4; nt++){
                int col = colBase + wnBase + nt*8 + cq;
                float e0 = __expf(fminf(acc[mt][nt][0], 70.f));
                float e1 = __expf(fminf(acc[mt][nt][1], 70.f));
                float e2 = __expf(fminf(acc[mt][nt][2], 70.f));
                float e3 = __expf(fminf(acc[mt][nt][3], 70.f));
                s0 += e0 + e1; s1 += e2 + e3;
                *(__nv_bfloat162*)(Eout + (size_t)r0*Vc + col) =
                    __float22bfloat162_rn(make_float2(e0, e1));
                *(__nv_bfloat162*)(Eout + (size_t)(r0+8)*Vc + col) =
                    __float22bfloat162_rn(make_float2(e2, e3));
            }
            s0 += __shfl_xor_sync(0xffffffffu, s0, 1);
            s0 += __shfl_xor_sync(0xffffffffu, s0, 2);
            s1 += __shfl_xor_sync(0xffffffffu, s1, 1);
            s1 += __shfl_xor_sync(0xffffffffu, s1, 2);
            if ((lane & 3) == 0){
                denm[lr0*4 + wn] = s0;
                denm[(lr0+8)*4 + wn] = s1;
            }
        }
        __syncthreads();
        if (tid < 128){
            float d = denm[tid*4] + denm[tid*4+1] + denm[tid*4+2] + denm[tid*4+3];
            denPart[(size_t)blockIdx.x * Rc + rowBase + tid] = d;
        }
    } else if (MODE == 1 || MODE == 5){
#pragma unroll
        for (int mt = 0; mt < 4; mt++){
            int r0 = rowBase + wmBase + mt*16 + (lane >> 2);
#pragma unroll
            for (int nt = 0; nt < 4; nt++){
                int col = colBase + wnBase + nt*8 + cq;
                *(float2*)(Cout + (size_t)r0*ldC + col) =
                    make_float2(acc[mt][nt][0], acc[mt][nt][1]);
                *(float2*)(Cout + (size_t)(r0+8)*ldC + col) =
                    make_float2(acc[mt][nt][2], acc[mt][nt][3]);
            }
        }
    } else if (MODE == 2){
#pragma unroll
        for (int mt = 0; mt < 4; mt++){
            int r0 = rowBase + wmBase + mt*16 + (lane >> 2);
#pragma unroll
            for (int nt = 0; nt < 4; nt++){
                int col = colBase + wnBase + nt*8 + cq;
                *(__nv_bfloat162*)(Eout + (size_t)r0*ldC + col) =
                    __float22bfloat162_rn(make_float2(acc[mt][nt][0], acc[mt][nt][1]));
                *(__nv_bfloat162*)(Eout + (size_t)(r0+8)*ldC + col) =
                    __float22bfloat162_rn(make_float2(acc[mt][nt][2], acc[mt][nt][3]));
            }
        }
    } else if (MODE == 3){
        int pat = (pattern == 2) ? zhi : pattern;
#pragma unroll
        for (int mt = 0; mt < 4; mt++){
            int r0 = rowBase + wmBase + mt*16 + (lane >> 2);
#pragma unroll
            for (int nt = 0; nt < 4; nt++){
                int col = colBase + wnBase + nt*8 + cq;
                float v0 = acc[mt][nt][0], v1 = acc[mt][nt][1];
                float v2 = acc[mt][nt][2], v3 = acc[mt][nt][3];
                __nv_bfloat16 h0 = __float2bfloat16(v0), h1 = __float2bfloat16(v1);
                __nv_bfloat16 h2 = __float2bfloat16(v2), h3 = __float2bfloat16(v3);
                __nv_bfloat16 l0 = __float2bfloat16(v0 - __bfloat162float(h0));
                __nv_bfloat16 l1 = __float2bfloat16(v1 - __bfloat162float(h1));
                __nv_bfloat16 l2 = __float2bfloat16(v2 - __bfloat162float(h2));
                __nv_bfloat16 l3 = __float2bfloat16(v3 - __bfloat162float(h3));
                __nv_bfloat162 hp0 = __halves2bfloat162(h0, h1);
                __nv_bfloat162 lp0 = __halves2bfloat162(l0, l1);
                __nv_bfloat162 hp1 = __halves2bfloat162(h2, h3);
                __nv_bfloat162 lp1 = __halves2bfloat162(l2, l3);
                __nv_bfloat16* rr0 = Eout + (size_t)r0*ldC + col;
                __nv_bfloat16* rr1 = Eout + (size_t)(r0+8)*ldC + col;
                *(__nv_bfloat162*)(rr0) = hp0;
                *(__nv_bfloat162*)(rr1) = hp1;
                if (pat == 0){
                    *(__nv_bfloat162*)(rr0 + seg)   = hp0;
                    *(__nv_bfloat162*)(rr0 + 2*seg) = lp0;
                    *(__nv_bfloat162*)(rr1 + seg)   = hp1;
                    *(__nv_bfloat162*)(rr1 + 2*seg) = lp1;
                } else {
                    *(__nv_bfloat162*)(rr0 + seg)   = lp0;
                    *(__nv_bfloat162*)(rr0 + 2*seg) = hp0;
                    *(__nv_bfloat162*)(rr1 + seg)   = lp1;
                    *(__nv_bfloat162*)(rr1 + 2*seg) = hp1;
                }
            }
        }
    }
}

// ---------------- reductions / elementwise ----------------
__device__ __forceinline__ float warpSum(float v) {
#pragma unroll
    for (int o = 16; o; o >>= 1) v += __shfl_xor_sync(0xffffffffu, v, o);
    return v;
}
__device__ __forceinline__ float warpMax(float v) {
#pragma unroll
    for (int o = 16; o; o >>= 1) v = fmaxf(v, __shfl_xor_sync(0xffffffffu, v, o));
    return v;
}

__global__ void ln_rows(const float* __restrict__ base, const int* __restrict__ idx,
                        const float* __restrict__ g, float* __restrict__ dst,
                        long rowStride)
{
    int row = blockIdx.x;
    const float* src = base + (idx ? (size_t)idx[row] * rowStride
                                   : (size_t)row * rowStride);
    int tid = threadIdx.x, lane = tid & 31, w = tid >> 5;
    __shared__ float sb[8];
    float v0 = src[tid], v1 = src[tid + 256];
    float s = warpSum(v0 + v1);
    if (lane == 0) sb[w] = s;
    __syncthreads();
    float tot = 0.f;
#pragma unroll
    for (int i = 0; i < 8; i++) tot += sb[i];
    float m = tot * (1.f / 512.f);
    float a0 = v0 - m, a1 = v1 - m;
    __syncthreads();
    float q = warpSum(a0*a0 + a1*a1);
    if (lane == 0) sb[w] = q;
    __syncthreads();
    float var = 0.f;
#pragma unroll
    for (int i = 0; i < 8; i++) var += sb[i];
    var *= (1.f / 512.f);
    float inv = rsqrtf(var + 1e-5f);
    float* dr = dst + (size_t)row * 512;
    dr[tid]       = a0 * inv * g[tid];
    dr[tid + 256] = a1 * inv * g[tid + 256];
}

// fused: LN(wpe row) -> split triple (hi,hi,lo) into p3
__global__ void ln_p3(const float* __restrict__ wpe, const float* __restrict__ g)
{
    int row = blockIdx.x;
    const float* src = wpe + (size_t)row * Dc;
    int tid = threadIdx.x, lane = tid & 31, w = tid >> 5;
    __shared__ float sb[8];
    float v0 = src[tid], v1 = src[tid + 256];
    float s = warpSum(v0 + v1);
    if (lane == 0) sb[w] = s;
    __syncthreads();
    float tot = 0.f;
#pragma unroll
    for (int i = 0; i < 8; i++) tot += sb[i];
    float m = tot * (1.f / 512.f);
    float a0 = v0 - m, a1 = v1 - m;
    __syncthreads();
    float q = warpSum(a0*a0 + a1*a1);
    if (lane == 0) sb[w] = q;
    __syncthreads();
    float var = 0.f;
#pragma unroll
    for (int i = 0; i < 8; i++) var += sb[i];
    var *= (1.f / 512.f);
    float inv = rsqrtf(var + 1e-5f);
    float x0 = a0 * inv * g[tid];
    float x1 = a1 * inv * g[tid + 256];
    __nv_bfloat16 h0 = __float2bfloat16(x0);
    __nv_bfloat16 l0 = __float2bfloat16(x0 - __bfloat162float(h0));
    __nv_bfloat16 h1 = __float2bfloat16(x1);
    __nv_bfloat16 l1 = __float2bfloat16(x1 - __bfloat162float(h1));
    __nv_bfloat16* r = d_p3 + (size_t)row * K3;
    r[tid] = h0;       r[512 + tid] = h0;       r[1024 + tid] = l0;
    r[tid + 256] = h1; r[768 + tid] = h1;       r[1280 + tid] = l1;
}

// fused: sum krn split-K partials, scale+clip+mask, softmax, *coef,
//        write split triple (hi,hi,lo) into krn3
__global__ void softmax_krn3()
{
    const float attnScale = 0.044194173824159216f;   // 1/sqrt(512)
    int row = blockIdx.x;                            // h*512 + s
    int s_idx = row & 511;
    const float* ra = d_krnp + (size_t)row * Sc;
    const float* rb = ra + (size_t)Hc * Sc * Sc;
    int tid = threadIdx.x, lane = tid & 31, w = tid >> 5;
    __shared__ float sb[8];
    float v0 = fminf(10.f, fmaxf(-10.f, (ra[tid] + rb[tid]) * attnScale));
    float v1 = fminf(10.f, fmaxf(-10.f, (ra[tid+256] + rb[tid+256]) * attnScale));
    if (tid > s_idx)       v0 = -INFINITY;
    if (tid + 256 > s_idx) v1 = -INFINITY;
    float m = warpMax(fmaxf(v0, v1));
    if (lane == 0) sb[w] = m;
    __syncthreads();
    float bm = sb[0];
#pragma unroll
    for (int i = 1; i < 8; i++) bm = fmaxf(bm, sb[i]);
    __syncthreads();
    float e0 = __expf(v0 - bm), e1 = __expf(v1 - bm);
    float s = warpSum(e0 + e1);
    if (lane == 0) sb[w] = s;
    __syncthreads();
    float bs = 0.f;
#pragma unroll
    for (int i = 0; i < 8; i++) bs += sb[i];
    float coef = 1.0f / (1.0f + (float)s_idx);
    float inv = coef / bs;
    float p0 = e0 * inv, p1 = e1 * inv;
    __nv_bfloat16 h0 = __float2bfloat16(p0);
    __nv_bfloat16 l0 = __float2bfloat16(p0 - __bfloat162float(h0));
    __nv_bfloat16 h1 = __float2bfloat16(p1);
    __nv_bfloat16 l1 = __float2bfloat16(p1 - __bfloat162float(h1));
    __nv_bfloat16* r3 = d_krn3 + (size_t)row * K3;
    r3[tid] = h0;  r3[512 + tid] = h0;  r3[1024 + tid] = l0;
    r3[tid + 256] = h1;  r3[768 + tid] = h1;  r3[1280 + tid] = l1;
}

__global__ void col_mean_part(const float* __restrict__ wte)
{
    int d = blockIdx.x * 128 + threadIdx.x;
    int z = blockIdx.y;
    float s = 0.f;
    int v0 = z * 1000;
    for (int v = v0; v < v0 + 1000; v++) s += wte[(size_t)v * Dc + d];
    d_cmeanp[z * Dc + d] = s;
}
__global__ void col_mean_reduce()
{
    int d = blockIdx.x * 128 + threadIdx.x;
    float s = 0.f;
#pragma unroll
    for (int z = 0; z < 32; z++) s += d_cmeanp[z * Dc + d];
    d_cmean[d] = s * (1.f / 32000.f);
}

__global__ void den_reduce()
{
    int r = blockIdx.x * 256 + threadIdx.x;
    float s = 0.f;
    for (int x = 0; x < Vc/128; x++) s += d_denp[(size_t)x * Rc + r];
    d_den[r] = s;
}

// fk += sum of 4 split-K partials (W_o); also refresh bf16 copy
__global__ void fk_combine()
{
    int i = blockIdx.x * 256 + threadIdx.x;
    float s = d_fk[i]
            + d_part[i]
            + d_part[(size_t)(Rc*Dc) + i]
            + d_part[2*(size_t)(Rc*Dc) + i]
            + d_part[3*(size_t)(Rc*Dc) + i];
    d_fk[i] = s;
    d_fk_bf[i] = __float2bfloat16(s);
}

// one-shot wte -> bf16 copy + bf16 transpose (single read of fp32)
__global__ void wte_convert(const float* __restrict__ w)
{
    __shared__ float t[32][33];
    int v0 = blockIdx.x * 32, d0 = blockIdx.y * 32;
    int tx = threadIdx.x, ty = threadIdx.y;
    for (int i = ty; i < 32; i += 8){
        float x = w[(size_t)(v0 + i) * Dc + d0 + tx];
        t[i][tx] = x;
        d_wte_bf[(size_t)(v0 + i) * Dc + d0 + tx] = __float2bfloat16(x);
    }
    __syncthreads();
    for (int i = ty; i < 32; i += 8)
        d_wteT_bf[(size_t)(d0 + i) * Vc + v0 + tx] = __float2bfloat16(t[tx][i]);
}

// ---- split-bf16 builders ----
__global__ void wqk3t_build(const float* __restrict__ W_q, const float* __restrict__ W_k)
{
    __shared__ float tl[32][33];
    int z = blockIdx.z;
    int h = z & 3, which = z >> 2;
    const float* src = (which ? W_k : W_q) + (size_t)h * Dc * Dc;
    __nv_bfloat16* dst = d_wqk3t + (size_t)which * Hc * Dc * K3 + (size_t)h * Dc * K3;
    int d0 = blockIdx.x * 32, e0 = blockIdx.y * 32;
    int tx = threadIdx.x, ty = threadIdx.y;
    for (int i = ty; i < 32; i += 8) tl[i][tx] = src[(size_t)(d0 + i) * Dc + e0 + tx];
    __syncthreads();
    for (int i = ty; i < 32; i += 8){
        float x = tl[tx][i];
        __nv_bfloat16 hi = __float2bfloat16(x);
        __nv_bfloat16 lo = __float2bfloat16(x - __bfloat162float(hi));
        __nv_bfloat16* row = dst + (size_t)(e0 + i) * K3;
        row[d0 + tx] = hi; row[512 + d0 + tx] = lo; row[1024 + d0 + tx] = hi;
    }
}

// vm3t[b][d][k] = split-transpose of (e - correction); triple (hi,lo,hi)
__global__ void vm3t_build(int layerN)
{
    __shared__ float tl[32][33];
    int b = blockIdx.z;
    int t0 = blockIdx.x * 32, d0 = blockIdx.y * 32;
    int tx = threadIdx.x, ty = threadIdx.y;
    for (int i = ty; i < 32; i += 8){
        int r = b * Sc + t0 + i;
        int d = d0 + tx;
        float corr;
        if (layerN){
            float num = 0.f;
#pragma unroll
            for (int z = 0; z < NSPLIT; z++)
                num += __bfloat162float(
                    d_partb[(size_t)z * ((size_t)Rc*Dc) + (size_t)r * Dc + d]);
            corr = num / d_den[r];
        } else {
            corr = d_cmean[d];
        }
        tl[i][tx] = d_e[(size_t)r * Dc + d] - corr;
    }
    __syncthreads();
    __nv_bfloat16* dst = d_vm3t + (size_t)b * Dc * K3;
    for (int i = ty; i < 32; i += 8){
        float x = tl[tx][i];
        __nv_bfloat16 hi = __float2bfloat16(x);
        __nv_bfloat16 lo = __float2bfloat16(x - __bfloat162float(hi));
        __nv_bfloat16* row = dst + (size_t)(d0 + i) * K3;
        row[t0 + tx] = hi; row[512 + t0 + tx] = lo; row[1024 + t0 + tx] = hi;
    }
}

__global__ void wo3t_build(const float* __restrict__ W_o)
{
    int i = blockIdx.x * 256 + threadIdx.x;
    int k = i & 2047, n = i >> 11;
    float x = W_o[i];
    __nv_bfloat16 hi = __float2bfloat16(x);
    __nv_bfloat16 lo = __float2bfloat16(x - __bfloat162float(hi));
    __nv_bfloat16* row = d_wo3t + (size_t)n * K6;
    row[k] = hi; row[2048 + k] = lo; row[4096 + k] = hi;
}

__global__ void logits_kernel(const float* __restrict__ last,
                              const float* __restrict__ wte,
                              float* __restrict__ out)
{
    int w = threadIdx.x >> 5, lane = threadIdx.x & 31;
    int v = blockIdx.x * 8 + w;
    int b = blockIdx.y;
    const float* q = last + b * 512;
    const float* wr = wte + (size_t)v * 512;
    float s = 0.f;
#pragma unroll
    for (int d = lane; d < 512; d += 32) s = fmaf(q[d], wr[d], s);
    s = warpSum(s);
    if (lane == 0) out[(size_t)b * Vc + v] = s;
}

// ---------------- launch ----------------
extern "C" void kernel_launch(void* const* d_in, const int* in_sizes, int n_in,
                              void* d_out, int out_size)
{
    const int*   x   = (const int*)  d_in[0];
    const float* wte = (const float*)d_in[1];
    const float* wpe = (const float*)d_in[2];
    const float* g_e = (const float*)d_in[3];
    const float* g_p = (const float*)d_in[4];
    const float* g_f = (const float*)d_in[5];
    const float* W_q = (const float*)d_in[6];
    const float* W_k = (const float*)d_in[7];
    const float* W_o = (const float*)d_in[8];
    float* out = (float*)d_out;

    float *e, *krnp, *fk, *part, *last, *denp;
    __nv_bfloat16 *E, *wte_bf, *wteT_bf, *fk_bf, *partb;
    __nv_bfloat16 *p3, *wqk3t, *QK3, *krn3, *vm3t, *delta3, *wo3t;
    cudaGetSymbolAddress((void**)&e,     d_e);
    cudaGetSymbolAddress((void**)&krnp,  d_krnp);
    cudaGetSymbolAddress((void**)&fk,    d_fk);
    cudaGetSymbolAddress((void**)&part,  d_part);
    cudaGetSymbolAddress((void**)&partb, d_partb);
    cudaGetSymbolAddress((void**)&last,  d_last);
    cudaGetSymbolAddress((void**)&denp,  d_denp);
    cudaGetSymbolAddress((void**)&E,       d_E);
    cudaGetSymbolAddress((void**)&wte_bf,  d_wte_bf);
    cudaGetSymbolAddress((void**)&wteT_bf, d_wteT_bf);
    cudaGetSymbolAddress((void**)&fk_bf,   d_fk_bf);
    cudaGetSymbolAddress((void**)&p3,      d_p3);
    cudaGetSymbolAddress((void**)&wqk3t,   d_wqk3t);
    cudaGetSymbolAddress((void**)&QK3,     d_QK3);
    cudaGetSymbolAddress((void**)&krn3,    d_krn3);
    cudaGetSymbolAddress((void**)&vm3t,    d_vm3t);
    cudaGetSymbolAddress((void**)&delta3,  d_delta3);
    cudaGetSymbolAddress((void**)&wo3t,    d_wo3t);

    cudaFuncSetAttribute(mma_core<0>, cudaFuncAttributeMaxDynamicSharedMemorySize, CORE_SMEM);
    cudaFuncSetAttribute(mma_core<1>, cudaFuncAttributeMaxDynamicSharedMemorySize, CORE_SMEM);
    cudaFuncSetAttribute(mma_core<2>, cudaFuncAttributeMaxDynamicSharedMemorySize, CORE_SMEM);
    cudaFuncSetAttribute(mma_core<3>, cudaFuncAttributeMaxDynamicSharedMemorySize, CORE_SMEM);
    cudaFuncSetAttribute(mma_core<5>, cudaFuncAttributeMaxDynamicSharedMemorySize, CORE_SMEM);

    // side stream + events (host objects only; created per call, few calls total)
    cudaStream_t s2;
    cudaStreamCreateWithFlags(&s2, cudaStreamNonBlocking);
    cudaEvent_t evFork, evJoin, evA[3], evB[3];
    cudaEventCreateWithFlags(&evFork, cudaEventDisableTiming);
    cudaEventCreateWithFlags(&evJoin, cudaEventDisableTiming);
    for (int i = 0; i < 3; i++){
        cudaEventCreateWithFlags(&evA[i], cudaEventDisableTiming);
        cudaEventCreateWithFlags(&evB[i], cudaEventDisableTiming);
    }

    const long SS = (long)Sc * Sc;

    // ---- fork: QK chain on side stream ----
    cudaEventRecord(evFork, 0);
    cudaStreamWaitEvent(s2, evFork, 0);
    ln_p3<<<Sc+1, 256, 0, s2>>>(wpe, g_p);
    wqk3t_build<<<dim3(16,16,8), dim3(32,8), 0, s2>>>(W_q, W_k);
    // QK3: z = which*4 + h;  Q (which=0): A = p3+K3, pattern 0
    //                        K (which=1): A = p3   , pattern 1
    mma_core<3><<<dim3(4,4,8), 256, CORE_SMEM, s2>>>(
        p3 + K3, (long)K3, wqk3t, (long)K3, K3/64,
        QK3, nullptr, nullptr, (long)K3,
        4, 0, -(long)K3,
        (long)Dc*K3, (long)Hc*Dc*K3,
        (long)Sc*K3, (long)Hc*Sc*K3,
        2, 512, 0, 0.f);
    // krn raw partials: z = chunk*4 + h; chunk selects k half via +768 offsets
    mma_core<5><<<dim3(4,4,8), 256, CORE_SMEM, s2>>>(
        QK3, (long)K3, QK3 + (size_t)Hc*Sc*K3, (long)K3, 768/64,
        nullptr, nullptr, krnp, (long)Sc,
        4, (long)Sc*K3, 768,
        (long)Sc*K3, 768,
        SS, (long)Hc*SS,
        0, 0, 0, 0.f);
    softmax_krn3<<<Hc*Sc, 256, 0, s2>>>();
    cudaEventRecord(evJoin, s2);

    // ---- main stream: embeddings + conversions (concurrent with QK chain) ----
    ln_rows<<<Rc, 256>>>(wte, x, g_e, e, (long)Dc);
    col_mean_part<<<dim3(4, 32), 128>>>(wte);
    col_mean_reduce<<<4, 128>>>();
    wte_convert<<<dim3(Vc/32, Dc/32), dim3(32, 8)>>>(wte);
    wo3t_build<<<(Dc*HDc)/256, 256>>>(W_o);
    cudaMemsetAsync(fk, 0, (size_t)Rc * Dc * sizeof(float), 0);
    cudaMemsetAsync(fk_bf, 0, (size_t)Rc * Dc * sizeof(__nv_bfloat16), 0);

    // join QK chain before layer loop (krn3 needed by delta)
    cudaStreamWaitEvent(0, evJoin, 0);

    for (int layer = 0; layer < 4; layer++) {
        if (layer > 0) {
            // E = exp(f_k @ wte^T), fused row-sum partials (K=512 -> 8 tiles)
            mma_core<0><<<dim3(Vc/128, Rc/128, 1), 256, CORE_SMEM>>>(
                fk_bf, (long)Dc, wte_bf, (long)Dc, Dc/64,
                E, denp, nullptr, 0, 1, 0,0,0,0,0,0, 0,0,0,0.f);
            // den_reduce rides the side stream, overlapped with GEMM2
            cudaEventRecord(evA[layer-1], 0);
            cudaStreamWaitEvent(s2, evA[layer-1], 0);
            den_reduce<<<Rc/256, 256, 0, s2>>>();
            cudaEventRecord(evB[layer-1], s2);
            // num = E @ wte (split-K over NSPLIT chunks; bf16 partials)
            mma_core<2><<<dim3(Dc/128, Rc/128, NSPLIT), 256, CORE_SMEM>>>(
                E, (long)Vc, wteT_bf, (long)Vc, (Vc/NSPLIT)/64,
                partb, nullptr, nullptr, (long)Dc, 1, 0,0,0,0,0,0, 0,0,0,0.f);
            cudaStreamWaitEvent(0, evB[layer-1], 0);
        }
        // vm3t = split-transpose(e - ex_wte)  (fused combine)
        vm3t_build<<<dim3(16,16,4), dim3(32,8)>>>(layer > 0 ? 1 : 0);
        // delta3 = split(krn3[h] @ vm3t[b]^T) (coef pre-folded into krn3)
        mma_core<3><<<dim3(4,4,16), 256, CORE_SMEM>>>(
            krn3, (long)K3, vm3t, (long)K3, K3/64,
            delta3, nullptr, nullptr, (long)K6,
            4, (long)Sc*K3, 0, 0, (long)Dc*K3, (long)Dc, (long)Sc*K6,
            0, 2048, 0, 0.f);
        // f_k += delta @ W_o^T (4-way split-K; fp32 partials)
        mma_core<1><<<dim3(Dc/128, Rc/128, 4), 256, CORE_SMEM>>>(
            delta3, (long)K6, wo3t, (long)K6, K6/(4*64),
            nullptr, nullptr, part, (long)Dc, 1, 0,0,0,0,0,0, 0,0,0,0.f);
        fk_combine<<<Rc*Dc/256, 256>>>();
    }

    ln_rows<<<Bc, 256>>>(fk + (size_t)(Sc-1)*Dc, nullptr, g_f, last, (long)Sc*Dc);
    logits_kernel<<<dim3(Vc/8, Bc), 256>>>(last, wte, out);
}